// round 16
// baseline (speedup 1.0000x reference)
#include <cuda_runtime.h>
#include <cuda_fp16.h>
#include <math.h>

#define BSZ 2
#define SSZ 2048
#define DSZ 1024
#define HN  16
#define DK  64
#define NPAIR 32

__device__ __half g_Q[BSZ*HN*SSZ*DK];
__device__ __half g_K[BSZ*HN*SSZ*DK];
__device__ __half g_V[BSZ*HN*SSZ*DK];   // TRANSPOSED: [B,H,dk,S]
__device__ __half g_O[BSZ*SSZ*DSZ];
__device__ __half g_X[BSZ*SSZ*DSZ];
__device__ __half g_Wq[DSZ*DSZ];
__device__ __half g_Wk[DSZ*DSZ];
__device__ __half g_Wv[DSZ*DSZ];
__device__ __half g_Wo[DSZ*DSZ];
__device__ float g_cos[SSZ*NPAIR];
__device__ float g_sin[SSZ*NPAIR];

// ---------------------------------------------------------------------------
// helpers
// ---------------------------------------------------------------------------
__device__ __forceinline__ float ex2(float x) {
    float y;
    asm("ex2.approx.f32 %0, %1;" : "=f"(y) : "f"(x));
    return y;
}

__device__ __forceinline__ void mma16(float* c, const unsigned* a, const unsigned* b) {
    asm volatile(
        "mma.sync.aligned.m16n8k16.row.col.f32.f16.f16.f32 "
        "{%0,%1,%2,%3}, {%4,%5,%6,%7}, {%8,%9}, {%0,%1,%2,%3};"
        : "+f"(c[0]), "+f"(c[1]), "+f"(c[2]), "+f"(c[3])
        : "r"(a[0]), "r"(a[1]), "r"(a[2]), "r"(a[3]), "r"(b[0]), "r"(b[1]));
}

__device__ __forceinline__ void cpa16(void* s, const void* g) {
    unsigned sa = (unsigned)__cvta_generic_to_shared(s);
    asm volatile("cp.async.cg.shared.global [%0], [%1], 16;" :: "r"(sa), "l"(g));
}
__device__ __forceinline__ void cpa_commit() {
    asm volatile("cp.async.commit_group;");
}
template <int N>
__device__ __forceinline__ void cpa_wait() {
    asm volatile("cp.async.wait_group %0;" :: "n"(N));
}

// ---------------------------------------------------------------------------
// fp32 -> fp16 cast pass: x + 4 weight matrices, 8 floats per thread
// ---------------------------------------------------------------------------
#define NX8 (BSZ*SSZ*DSZ/8)
#define NW8 (DSZ*DSZ/8)

__global__ void cast_all_kernel(const float4* __restrict__ x,
                                const float4* __restrict__ wq,
                                const float4* __restrict__ wk,
                                const float4* __restrict__ wv,
                                const float4* __restrict__ wo) {
    int i = blockIdx.x * blockDim.x + threadIdx.x;
    if (i >= NX8 + 4 * NW8) return;
    const float4* src;
    __half* dst;
    int off;
    if (i < NX8) {
        src = x; dst = g_X; off = i;
    } else {
        int j = i - NX8;
        int wsel = j / NW8;
        off = j - wsel * NW8;
        src = (wsel == 0 ? wq : wsel == 1 ? wk : wsel == 2 ? wv : wo);
        dst = (wsel == 0 ? g_Wq : wsel == 1 ? g_Wk : wsel == 2 ? g_Wv : g_Wo);
    }
    float4 a = src[2 * off], b = src[2 * off + 1];
    __half2 h0 = __floats2half2_rn(a.x, a.y);
    __half2 h1 = __floats2half2_rn(a.z, a.w);
    __half2 h2 = __floats2half2_rn(b.x, b.y);
    __half2 h3 = __floats2half2_rn(b.z, b.w);
    uint4 pack;
    pack.x = *(unsigned*)&h0; pack.y = *(unsigned*)&h1;
    pack.z = *(unsigned*)&h2; pack.w = *(unsigned*)&h3;
    *((uint4*)dst + off) = pack;
}

// ---------------------------------------------------------------------------
// RoPE table
// ---------------------------------------------------------------------------
__global__ void rope_table_kernel() {
    int i = blockIdx.x * blockDim.x + threadIdx.x;
    if (i >= SSZ * NPAIR) return;
    int s = i >> 5, p = i & 31;
    double ang = (double)s * exp(-(double)p * (9.210340371976184 / 32.0));
    g_cos[i] = (float)cos(ang);
    g_sin[i] = (float)sin(ang);
}

// ---------------------------------------------------------------------------
// fp16 NT-GEMM: C[256x128] = A[256x1024] * W[128x1024]^T
// 256 thr / 8 warps in 4x2, warp tile 64x64, BK=32 halves, 3-stage cp.async,
// fragment double-buffer across the 2 k16-steps per stage.
// Loader: 4 threads per row (c8 in {0,8,16,24}) — 32 halves per row.
// ---------------------------------------------------------------------------
#define GST 40           // halves per smem row
#define GSTW 20          // 32-bit words per smem row
#define GSTG 3
#define ABUF (256*GST)   // A halves per stage
#define BBUF (128*GST)   // B halves per stage
#define SBUF (ABUF+BBUF)
#define NKT 32

struct GemmCtx { int g, t, wm, wn; };

__device__ __forceinline__ void gemm_issue(
    __half* Sm, int st,
    const __half* __restrict__ A, const __half* __restrict__ W,
    int m0, int n0, int kh)
{
    __half* as = Sm + st * SBUF;
    __half* bs = as + ABUF;
    const int r0 = threadIdx.x >> 2;        // 0..63
    const int c8 = (threadIdx.x & 3) << 3;  // 0,8,16,24
#pragma unroll
    for (int i = 0; i < 4; i++) {
        int r = r0 + 64 * i;                // A rows 0..255
        cpa16(&as[r * GST + c8], A + (size_t)(m0 + r) * 1024 + kh + c8);
    }
#pragma unroll
    for (int i = 0; i < 2; i++) {
        int r = r0 + 64 * i;                // B rows 0..127
        cpa16(&bs[r * GST + c8], W + (size_t)(n0 + r) * 1024 + kh + c8);
    }
}

__device__ __forceinline__ void gemm_ldfrag(
    const __half* as, const __half* bs, int ks,
    unsigned (&af)[4][4], unsigned (&bf)[8][2], const GemmCtx& cx)
{
    const unsigned* aw = (const unsigned*)as;
    const unsigned* bw = (const unsigned*)bs;
    const int k0 = ks * 8;
#pragma unroll
    for (int mt = 0; mt < 4; mt++) {
        int base = (cx.wm + mt*16 + cx.g) * GSTW + k0 + cx.t;
        af[mt][0] = aw[base];
        af[mt][1] = aw[base + 8*GSTW];
        af[mt][2] = aw[base + 4];
        af[mt][3] = aw[base + 8*GSTW + 4];
    }
#pragma unroll
    for (int nt = 0; nt < 8; nt++) {
        int base = (cx.wn + nt*8 + cx.g) * GSTW + k0 + cx.t;
        bf[nt][0] = bw[base];
        bf[nt][1] = bw[base + 4];
    }
}

__device__ __forceinline__ void gemm_main(
    const __half* __restrict__ A, const __half* __restrict__ W,
    int m0, int n0, float (&acc)[4][8][4],
    __half* Sm, const GemmCtx& cx)
{
#pragma unroll
    for (int s = 0; s < GSTG - 1; s++) {
        gemm_issue(Sm, s, A, W, m0, n0, s * 32);
        cpa_commit();
    }
    unsigned af[2][4][4], bf[2][8][2];
    for (int kb = 0; kb < NKT; kb++) {
        cpa_wait<GSTG - 2>();
        __syncthreads();
        if (kb + GSTG - 1 < NKT)
            gemm_issue(Sm, (kb + GSTG - 1) % GSTG, A, W, m0, n0, (kb + GSTG - 1) * 32);
        cpa_commit();

        const __half* as = Sm + (kb % GSTG) * SBUF;
        const __half* bs = as + ABUF;
        gemm_ldfrag(as, bs, 0, af[0], bf[0], cx);
#pragma unroll
        for (int ks = 0; ks < 2; ks++) {
            const int cur = ks & 1;
            if (ks < 1)
                gemm_ldfrag(as, bs, ks + 1, af[cur ^ 1], bf[cur ^ 1], cx);
#pragma unroll
            for (int nt = 0; nt < 8; nt++)
#pragma unroll
                for (int mt = 0; mt < 4; mt++)
                    mma16(acc[mt][nt], af[cur][mt], bf[cur][nt]);
        }
    }
}

// QKV projection: fused RoPE (Q,K), fused softmax scale (Q), V transposed.
__global__ __launch_bounds__(256) void gemm_qkv_kernel()
{
    extern __shared__ __half smh[];

    const int z = blockIdx.z;
    const __half* W = z == 0 ? g_Wq : (z == 1 ? g_Wk : g_Wv);
    __half* dst     = z == 0 ? g_Q  : (z == 1 ? g_K  : g_V);

    const int lane = threadIdx.x & 31;
    const int wid = threadIdx.x >> 5;
    GemmCtx cx;
    cx.g = lane >> 2; cx.t = lane & 3;
    cx.wm = (wid & 3) * 64; cx.wn = (wid >> 2) * 64;
    const int m0 = blockIdx.y * 256, n0 = blockIdx.x * 128;

    float acc[4][8][4];
#pragma unroll
    for (int i = 0; i < 4; i++)
#pragma unroll
        for (int j = 0; j < 8; j++)
#pragma unroll
            for (int k = 0; k < 4; k++) acc[i][j][k] = 0.f;

    gemm_main(g_X, W, m0, n0, acc, smh, cx);

    const float qsc = 0.125f * 1.4426950408889634f;   // 1/sqrt(dk) * log2(e)
#pragma unroll
    for (int mt = 0; mt < 4; mt++) {
        int m = m0 + cx.wm + mt * 16 + cx.g;
        int b = m >> 11, s = m & (SSZ - 1);
#pragma unroll
        for (int nt = 0; nt < 8; nt++) {
            int n = n0 + cx.wn + nt * 8 + 2 * cx.t;
            int h = n >> 6, c = n & 63;
            float v0 = acc[mt][nt][0], v1 = acc[mt][nt][1];
            float v2 = acc[mt][nt][2], v3 = acc[mt][nt][3];
            if (z == 2) {
                __half* dv = dst + (((size_t)(b * HN + h)) * DK + c) * SSZ + s;
                dv[0]       = __float2half_rn(v0);
                dv[SSZ]     = __float2half_rn(v1);
                dv[8]       = __float2half_rn(v2);
                dv[SSZ + 8] = __float2half_rn(v3);
            } else {
                int p = c >> 1;
                float ca0 = g_cos[(s << 5) | p],       sa0 = g_sin[(s << 5) | p];
                float ca1 = g_cos[((s + 8) << 5) | p], sa1 = g_sin[((s + 8) << 5) | p];
                float r0 = v0 * ca0 - v1 * sa0;
                float r1 = v0 * sa0 + v1 * ca0;
                float r2 = v2 * ca1 - v3 * sa1;
                float r3 = v2 * sa1 + v3 * ca1;
                if (z == 0) { r0 *= qsc; r1 *= qsc; r2 *= qsc; r3 *= qsc; }
                __half* base = dst + (((size_t)(b * HN + h) * SSZ)) * DK + c;
                *(__half2*)(base + (size_t)s * DK)       = __floats2half2_rn(r0, r1);
                *(__half2*)(base + (size_t)(s + 8) * DK) = __floats2half2_rn(r2, r3);
            }
        }
    }
}

// Output projection: out = g_O @ g_Wo^T, fp32 result
__global__ __launch_bounds__(256) void gemm_out_kernel(float* __restrict__ C)
{
    extern __shared__ __half smh[];

    const int lane = threadIdx.x & 31;
    const int wid = threadIdx.x >> 5;
    GemmCtx cx;
    cx.g = lane >> 2; cx.t = lane & 3;
    cx.wm = (wid & 3) * 64; cx.wn = (wid >> 2) * 64;
    const int m0 = blockIdx.y * 256, n0 = blockIdx.x * 128;

    float acc[4][8][4];
#pragma unroll
    for (int i = 0; i < 4; i++)
#pragma unroll
        for (int j = 0; j < 8; j++)
#pragma unroll
            for (int k = 0; k < 4; k++) acc[i][j][k] = 0.f;

    gemm_main(g_O, g_Wo, m0, n0, acc, smh, cx);

#pragma unroll
    for (int mt = 0; mt < 4; mt++) {
        int m = m0 + cx.wm + mt * 16 + cx.g;
#pragma unroll
        for (int nt = 0; nt < 8; nt++) {
            int n = n0 + cx.wn + nt * 8 + 2 * cx.t;
            *(float2*)(C + (size_t)m * 1024 + n)       = make_float2(acc[mt][nt][0], acc[mt][nt][1]);
            *(float2*)(C + (size_t)(m + 8) * 1024 + n) = make_float2(acc[mt][nt][2], acc[mt][nt][3]);
        }
    }
}

// ---------------------------------------------------------------------------
// fp16 flash attention (EXACT R11 best): 128 thr / 4 warps, BQ=128, BK=64.
// Q frags direct from gmem (pre-scaled); V transposed in gmem.
// smem: sP[128][72], sK[2][64][72], sVt[2][64][72] halves (54 KB).
// exp2 softmax, deferred l-reduction, whole-warp masked-block skip.
// ---------------------------------------------------------------------------
#define AST 72     // halves per smem row
#define ASTW 36    // words per smem row
#define AKBUF (64*AST)

__global__ __launch_bounds__(128) void attn_kernel() {
    extern __shared__ __half smh[];
    __half* sP  = smh;                   // 128*72
    __half* sK0 = smh + 128*AST;         // 2 x 64*72
    __half* sV0 = smh + 128*AST + 2*AKBUF;

    const int tid = threadIdx.x;
    const int w = tid >> 5;
    const int lane = tid & 31;
    const int g = lane >> 2, t = lane & 3;
    const int qb = (int)gridDim.x - 1 - (int)blockIdx.x;   // heavy CTAs first
    const int bh = blockIdx.y;
    const __half* Qg  = g_Q + (size_t)bh * SSZ * DK;
    const __half* Kg  = g_K + (size_t)bh * SSZ * DK;
    const __half* Vtg = g_V + (size_t)bh * DK * SSZ;       // [dk][S]
    const int kb_max = 2 * qb + 1;
    const int warp_row_max = qb * 128 + w * 32 + 31;

    // prologue: issue K/V block 0 loads (64 rows x 64 halves each)
#pragma unroll
    for (int i = 0; i < 4; i++) {
        int e = i * 128 + tid;
        int r = e >> 3, c8 = (e & 7) << 3;
        cpa16(&sK0[r * AST + c8], Kg + (size_t)r * DK + c8);
        cpa16(&sV0[r * AST + c8], Vtg + (size_t)r * SSZ + c8);
    }
    cpa_commit();

    // Q fragments direct from gmem (already scaled, fp16)
    unsigned qf[2][4][4];
#pragma unroll
    for (int mt = 0; mt < 2; mt++) {
        int q0 = qb * 128 + w * 32 + mt * 16 + g;
#pragma unroll
        for (int ks = 0; ks < 4; ks++) {
            const __half* p = Qg + (size_t)q0 * DK + ks * 16 + 2 * t;
            qf[mt][ks][0] = *(const unsigned*)(p);
            qf[mt][ks][1] = *(const unsigned*)(p + 8 * DK);
            qf[mt][ks][2] = *(const unsigned*)(p + 8);
            qf[mt][ks][3] = *(const unsigned*)(p + 8 * DK + 8);
        }
    }

    float mrun[2][2] = {{-1e30f, -1e30f}, {-1e30f, -1e30f}};
    float lrun[2][2] = {{0.f, 0.f}, {0.f, 0.f}};
    float oacc[2][8][4];
#pragma unroll
    for (int mt = 0; mt < 2; mt++)
#pragma unroll
        for (int nt = 0; nt < 8; nt++)
#pragma unroll
            for (int k = 0; k < 4; k++) oacc[mt][nt][k] = 0.f;

    for (int kb = 0; kb <= kb_max; kb++) {
        __syncthreads();   // buffer (kb+1)&1 free
        if (kb < kb_max) {
            __half* sK = sK0 + ((kb + 1) & 1) * AKBUF;
            __half* sV = sV0 + ((kb + 1) & 1) * AKBUF;
#pragma unroll
            for (int i = 0; i < 4; i++) {
                int e = i * 128 + tid;
                int r = e >> 3, c8 = (e & 7) << 3;
                cpa16(&sK[r * AST + c8], Kg + (size_t)((kb + 1) * 64 + r) * DK + c8);
                cpa16(&sV[r * AST + c8], Vtg + (size_t)r * SSZ + (kb + 1) * 64 + c8);
            }
        }
        cpa_commit();
        cpa_wait<1>();
        __syncthreads();

        // whole-warp skip: entire q-tile above the diagonal
        if (kb * 64 > warp_row_max) continue;

        const unsigned* kw = (const unsigned*)(sK0 + (kb & 1) * AKBUF);
        const unsigned* vw = (const unsigned*)(sV0 + (kb & 1) * AKBUF);

        // S = Q K^T : 4 k16-steps over dk, 8 n-tiles over kv
        float s[2][8][4];
#pragma unroll
        for (int mt = 0; mt < 2; mt++)
#pragma unroll
            for (int nt = 0; nt < 8; nt++)
#pragma unroll
                for (int k = 0; k < 4; k++) s[mt][nt][k] = 0.f;

#pragma unroll
        for (int ks = 0; ks < 4; ks++) {
            unsigned kf[8][2];
#pragma unroll
            for (int nt = 0; nt < 8; nt++) {
                int base = (nt * 8 + g) * ASTW + ks * 8 + t;
                kf[nt][0] = kw[base];
                kf[nt][1] = kw[base + 4];
            }
#pragma unroll
            for (int nt = 0; nt < 8; nt++) {
                mma16(s[0][nt], qf[0][ks], kf[nt]);
                mma16(s[1][nt], qf[1][ks], kf[nt]);
            }
        }

        // causal mask
        if (kb >= 2 * qb) {
#pragma unroll
            for (int mt = 0; mt < 2; mt++) {
                int qg = qb * 128 + w * 32 + mt * 16 + g;
#pragma unroll
                for (int nt = 0; nt < 8; nt++) {
                    int col = kb * 64 + nt * 8 + 2 * t;
                    if (col     > qg)     s[mt][nt][0] = -1e30f;
                    if (col + 1 > qg)     s[mt][nt][1] = -1e30f;
                    if (col     > qg + 8) s[mt][nt][2] = -1e30f;
                    if (col + 1 > qg + 8) s[mt][nt][3] = -1e30f;
                }
            }
        }

        __syncwarp();   // this warp's prior PV reads of its P rows done

        // online softmax (exp2 domain), deferred l-reduction
#pragma unroll
        for (int mt = 0; mt < 2; mt++) {
            const int qr = w * 32 + mt * 16 + g;
#pragma unroll
            for (int r = 0; r < 2; r++) {
                float mx = -1e30f;
#pragma unroll
                for (int nt = 0; nt < 8; nt++)
                    mx = fmaxf(mx, fmaxf(s[mt][nt][2*r], s[mt][nt][2*r + 1]));
                mx = fmaxf(mx, __shfl_xor_sync(0xffffffffu, mx, 1));
                mx = fmaxf(mx, __shfl_xor_sync(0xffffffffu, mx, 2));
                float mnew = fmaxf(mrun[mt][r], mx);
                float corr = ex2(mrun[mt][r] - mnew);
                float rs = 0.f;
                __half* prow = sP + (qr + 8 * r) * AST;
#pragma unroll
                for (int nt = 0; nt < 8; nt++) {
                    float p0 = ex2(s[mt][nt][2*r]     - mnew);
                    float p1 = ex2(s[mt][nt][2*r + 1] - mnew);
                    rs += p0 + p1;
                    *(__half2*)(prow + nt * 8 + 2 * t) = __floats2half2_rn(p0, p1);
                }
                lrun[mt][r] = lrun[mt][r] * corr + rs;
                mrun[mt][r] = mnew;
#pragma unroll
                for (int nt = 0; nt < 8; nt++) {
                    oacc[mt][nt][2*r]     *= corr;
                    oacc[mt][nt][2*r + 1] *= corr;
                }
            }
        }
        __syncwarp();

        // O += P V : 4 k16-steps over kv, 8 n-tiles over dk (V transposed)
        const unsigned* pw = (const unsigned*)sP;
#pragma unroll
        for (int ks = 0; ks < 4; ks++) {
            unsigned pf[2][4];
#pragma unroll
            for (int mt = 0; mt < 2; mt++) {
                int base = (w * 32 + mt * 16 + g) * ASTW + ks * 8 + t;
                pf[mt][0] = pw[base];
                pf[mt][1] = pw[base + 8 * ASTW];
                pf[mt][2] = pw[base + 4];
                pf[mt][3] = pw[base + 8 * ASTW + 4];
            }
            unsigned vf[8][2];
#pragma unroll
            for (int nt = 0; nt < 8; nt++) {
                int base = (nt * 8 + g) * ASTW + ks * 8 + t;
                vf[nt][0] = vw[base];
                vf[nt][1] = vw[base + 4];
            }
#pragma unroll
            for (int nt = 0; nt < 8; nt++) {
                mma16(oacc[0][nt], pf[0], vf[nt]);
                mma16(oacc[1][nt], pf[1], vf[nt]);
            }
        }
    }

    // epilogue: reduce deferred row sums, normalize, store fp16 to [B,S,D]
    const int b = bh >> 4;
    const int h = bh & 15;
#pragma unroll
    for (int mt = 0; mt < 2; mt++) {
#pragma unroll
        for (int r = 0; r < 2; r++) {
            float lsum = lrun[mt][r];
            lsum += __shfl_xor_sync(0xffffffffu, lsum, 1);
            lsum += __shfl_xor_sync(0xffffffffu, lsum, 2);
            float inv = 1.f / lsum;
            int q = qb * 128 + w * 32 + mt * 16 + g + 8 * r;
            __half* dst = g_O + ((size_t)b * SSZ + q) * DSZ + h * DK;
#pragma unroll
            for (int nt = 0; nt < 8; nt++)
                *(__half2*)(dst + nt * 8 + 2 * t) =
                    __floats2half2_rn(oacc[mt][nt][2*r] * inv,
                                      oacc[mt][nt][2*r + 1] * inv);
        }
    }
}

// ---------------------------------------------------------------------------
extern "C" void kernel_launch(void* const* d_in, const int* in_sizes, int n_in,
                              void* d_out, int out_size) {
    (void)in_sizes; (void)n_in; (void)out_size;
    const float* x  = (const float*)d_in[0];
    const float* Wq = (const float*)d_in[1];
    const float* Wk = (const float*)d_in[2];
    const float* Wv = (const float*)d_in[3];
    const float* Wo = (const float*)d_in[4];
    float* out = (float*)d_out;

    const int gemm_smem = GSTG * SBUF * (int)sizeof(__half);      // 92160 B
    cudaFuncSetAttribute(gemm_qkv_kernel, cudaFuncAttributeMaxDynamicSharedMemorySize, gemm_smem);
    cudaFuncSetAttribute(gemm_out_kernel, cudaFuncAttributeMaxDynamicSharedMemorySize, gemm_smem);
    const int attn_smem = (128*AST + 4*AKBUF) * (int)sizeof(__half);  // 55296 B
    cudaFuncSetAttribute(attn_kernel, cudaFuncAttributeMaxDynamicSharedMemorySize, attn_smem);

    rope_table_kernel<<<(SSZ * NPAIR + 255) / 256, 256>>>();

    const int NTOT8 = NX8 + 4 * NW8;
    cast_all_kernel<<<(NTOT8 + 255)/256, 256>>>(
        (const float4*)x, (const float4*)Wq, (const float4*)Wk,
        (const float4*)Wv, (const float4*)Wo);

    gemm_qkv_kernel<<<dim3(8, 16, 3), 256, gemm_smem>>>();
    attn_kernel<<<dim3(SSZ / 128, BSZ * HN), 128, attn_smem>>>();
    gemm_out_kernel<<<dim3(8, 16), 256, gemm_smem>>>(out);
}

// round 17
// speedup vs baseline: 1.1718x; 1.1718x over previous
#include <cuda_runtime.h>
#include <cuda_fp16.h>
#include <math.h>

#define BSZ 2
#define SSZ 2048
#define DSZ 1024
#define HN  16
#define DK  64
#define NPAIR 32

__device__ __half g_Q[BSZ*HN*SSZ*DK];
__device__ __half g_K[BSZ*HN*SSZ*DK];
__device__ __half g_V[BSZ*HN*SSZ*DK];   // TRANSPOSED: [B,H,dk,S]
__device__ __half g_O[BSZ*SSZ*DSZ];
__device__ __half g_X[BSZ*SSZ*DSZ];
__device__ __half g_Wq[DSZ*DSZ];
__device__ __half g_Wk[DSZ*DSZ];
__device__ __half g_Wv[DSZ*DSZ];
__device__ __half g_Wo[DSZ*DSZ];
__device__ float g_cos[SSZ*NPAIR];
__device__ float g_sin[SSZ*NPAIR];

// ---------------------------------------------------------------------------
// helpers
// ---------------------------------------------------------------------------
__device__ __forceinline__ float ex2(float x) {
    float y;
    asm("ex2.approx.f32 %0, %1;" : "=f"(y) : "f"(x));
    return y;
}

__device__ __forceinline__ void mma16(float* c, const unsigned* a, const unsigned* b) {
    asm volatile(
        "mma.sync.aligned.m16n8k16.row.col.f32.f16.f16.f32 "
        "{%0,%1,%2,%3}, {%4,%5,%6,%7}, {%8,%9}, {%0,%1,%2,%3};"
        : "+f"(c[0]), "+f"(c[1]), "+f"(c[2]), "+f"(c[3])
        : "r"(a[0]), "r"(a[1]), "r"(a[2]), "r"(a[3]), "r"(b[0]), "r"(b[1]));
}

__device__ __forceinline__ void ldsm4(unsigned& r0, unsigned& r1,
                                      unsigned& r2, unsigned& r3, unsigned addr) {
    asm volatile("ldmatrix.sync.aligned.m8n8.x4.shared.b16 {%0,%1,%2,%3}, [%4];"
        : "=r"(r0), "=r"(r1), "=r"(r2), "=r"(r3) : "r"(addr));
}

__device__ __forceinline__ void cpa16(void* s, const void* g) {
    unsigned sa = (unsigned)__cvta_generic_to_shared(s);
    asm volatile("cp.async.cg.shared.global [%0], [%1], 16;" :: "r"(sa), "l"(g));
}
__device__ __forceinline__ void cpa_commit() {
    asm volatile("cp.async.commit_group;");
}
template <int N>
__device__ __forceinline__ void cpa_wait() {
    asm volatile("cp.async.wait_group %0;" :: "n"(N));
}

// ---------------------------------------------------------------------------
// fp32 -> fp16 cast pass: x + 4 weight matrices, 8 floats per thread
// ---------------------------------------------------------------------------
#define NX8 (BSZ*SSZ*DSZ/8)
#define NW8 (DSZ*DSZ/8)

__global__ void cast_all_kernel(const float4* __restrict__ x,
                                const float4* __restrict__ wq,
                                const float4* __restrict__ wk,
                                const float4* __restrict__ wv,
                                const float4* __restrict__ wo) {
    int i = blockIdx.x * blockDim.x + threadIdx.x;
    if (i >= NX8 + 4 * NW8) return;
    const float4* src;
    __half* dst;
    int off;
    if (i < NX8) {
        src = x; dst = g_X; off = i;
    } else {
        int j = i - NX8;
        int wsel = j / NW8;
        off = j - wsel * NW8;
        src = (wsel == 0 ? wq : wsel == 1 ? wk : wsel == 2 ? wv : wo);
        dst = (wsel == 0 ? g_Wq : wsel == 1 ? g_Wk : wsel == 2 ? g_Wv : g_Wo);
    }
    float4 a = src[2 * off], b = src[2 * off + 1];
    __half2 h0 = __floats2half2_rn(a.x, a.y);
    __half2 h1 = __floats2half2_rn(a.z, a.w);
    __half2 h2 = __floats2half2_rn(b.x, b.y);
    __half2 h3 = __floats2half2_rn(b.z, b.w);
    uint4 pack;
    pack.x = *(unsigned*)&h0; pack.y = *(unsigned*)&h1;
    pack.z = *(unsigned*)&h2; pack.w = *(unsigned*)&h3;
    *((uint4*)dst + off) = pack;
}

// ---------------------------------------------------------------------------
// RoPE table
// ---------------------------------------------------------------------------
__global__ void rope_table_kernel() {
    int i = blockIdx.x * blockDim.x + threadIdx.x;
    if (i >= SSZ * NPAIR) return;
    int s = i >> 5, p = i & 31;
    double ang = (double)s * exp(-(double)p * (9.210340371976184 / 32.0));
    g_cos[i] = (float)cos(ang);
    g_sin[i] = (float)sin(ang);
}

// ---------------------------------------------------------------------------
// fp16 NT-GEMM (R11 geometry + ldmatrix fragment loads):
// C[128x128] = A[128x1024] * W[128x1024]^T
// 128 thr / 4 warps 2x2, warp tile 64x64, BK=32 halves, 3-stage cp.async.
// Row stride 40 halves: ldmatrix rows hit banks {0,20,8,28,16,4,24,12} - clean.
// ---------------------------------------------------------------------------
#define GST 40           // halves per smem row
#define GSTG 3
#define GBUF (128*GST)
#define NKT 32

struct GemmCtx {
    int wm, wn, g, t;
    int arow, akh;   // A-style ldmatrix lane offsets (row, k-half)
    int brow, bkh;   // B-style
};

__device__ __forceinline__ void gemm_issue(
    __half* As, __half* Bs, int st,
    const __half* __restrict__ A, const __half* __restrict__ W,
    int m0, int n0, int kh)
{
    __half* as = As + st * GBUF;
    __half* bs = Bs + st * GBUF;
    const int r0 = threadIdx.x >> 2;
    const int c8 = (threadIdx.x & 3) << 3;
#pragma unroll
    for (int i = 0; i < 4; i++) {
        int r = r0 + 32 * i;
        cpa16(&as[r * GST + c8], A + (size_t)(m0 + r) * 1024 + kh + c8);
        cpa16(&bs[r * GST + c8], W + (size_t)(n0 + r) * 1024 + kh + c8);
    }
}

__device__ __forceinline__ void gemm_ldfrag(
    unsigned as_byte, unsigned bs_byte, int ks,
    unsigned (&af)[4][4], unsigned (&bf)[8][2], const GemmCtx& cx)
{
#pragma unroll
    for (int mt = 0; mt < 4; mt++) {
        unsigned addr = as_byte +
            (unsigned)(((cx.wm + mt*16 + cx.arow) * GST + ks*16 + cx.akh) * 2);
        ldsm4(af[mt][0], af[mt][1], af[mt][2], af[mt][3], addr);
    }
#pragma unroll
    for (int np = 0; np < 4; np++) {
        unsigned addr = bs_byte +
            (unsigned)(((cx.wn + np*16 + cx.brow) * GST + ks*16 + cx.bkh) * 2);
        ldsm4(bf[2*np][0], bf[2*np][1], bf[2*np+1][0], bf[2*np+1][1], addr);
    }
}

__device__ __forceinline__ void gemm_main(
    const __half* __restrict__ A, const __half* __restrict__ W,
    int m0, int n0, float (&acc)[4][8][4],
    __half* As, __half* Bs, const GemmCtx& cx)
{
#pragma unroll
    for (int s = 0; s < GSTG - 1; s++) {
        gemm_issue(As, Bs, s, A, W, m0, n0, s * 32);
        cpa_commit();
    }
    const unsigned as0 = (unsigned)__cvta_generic_to_shared(As);
    const unsigned bs0 = (unsigned)__cvta_generic_to_shared(Bs);
    unsigned af[2][4][4], bf[2][8][2];
    for (int kb = 0; kb < NKT; kb++) {
        cpa_wait<GSTG - 2>();
        __syncthreads();
        if (kb + GSTG - 1 < NKT)
            gemm_issue(As, Bs, (kb + GSTG - 1) % GSTG, A, W, m0, n0, (kb + GSTG - 1) * 32);
        cpa_commit();

        const unsigned as_byte = as0 + (kb % GSTG) * GBUF * 2;
        const unsigned bs_byte = bs0 + (kb % GSTG) * GBUF * 2;
        gemm_ldfrag(as_byte, bs_byte, 0, af[0], bf[0], cx);
#pragma unroll
        for (int ks = 0; ks < 2; ks++) {
            const int cur = ks & 1;
            if (ks < 1)
                gemm_ldfrag(as_byte, bs_byte, ks + 1, af[cur ^ 1], bf[cur ^ 1], cx);
#pragma unroll
            for (int nt = 0; nt < 8; nt++)
#pragma unroll
                for (int mt = 0; mt < 4; mt++)
                    mma16(acc[mt][nt], af[cur][mt], bf[cur][nt]);
        }
    }
}

__device__ __forceinline__ GemmCtx make_gemm_ctx() {
    const int lane = threadIdx.x & 31;
    const int wid = threadIdx.x >> 5;
    GemmCtx cx;
    cx.g = lane >> 2; cx.t = lane & 3;
    cx.wm = (wid & 1) * 64; cx.wn = (wid >> 1) * 64;
    cx.arow = ((lane >> 3) & 1) * 8 + (lane & 7);
    cx.akh  = (lane >> 4) * 8;
    cx.brow = ((lane >> 4) & 1) * 8 + (lane & 7);
    cx.bkh  = ((lane >> 3) & 1) * 8;
    return cx;
}

// QKV projection: fused RoPE (Q,K), fused softmax scale (Q), V transposed.
__global__ __launch_bounds__(128) void gemm_qkv_kernel()
{
    extern __shared__ __half smh[];
    __half* As = smh;
    __half* Bs = smh + GSTG * GBUF;

    const int z = blockIdx.z;
    const __half* W = z == 0 ? g_Wq : (z == 1 ? g_Wk : g_Wv);
    __half* dst     = z == 0 ? g_Q  : (z == 1 ? g_K  : g_V);

    GemmCtx cx = make_gemm_ctx();
    const int m0 = blockIdx.y * 128, n0 = blockIdx.x * 128;

    float acc[4][8][4];
#pragma unroll
    for (int i = 0; i < 4; i++)
#pragma unroll
        for (int j = 0; j < 8; j++)
#pragma unroll
            for (int k = 0; k < 4; k++) acc[i][j][k] = 0.f;

    gemm_main(g_X, W, m0, n0, acc, As, Bs, cx);

    const float qsc = 0.125f * 1.4426950408889634f;   // 1/sqrt(dk) * log2(e)
#pragma unroll
    for (int mt = 0; mt < 4; mt++) {
        int m = m0 + cx.wm + mt * 16 + cx.g;
        int b = m >> 11, s = m & (SSZ - 1);
#pragma unroll
        for (int nt = 0; nt < 8; nt++) {
            int n = n0 + cx.wn + nt * 8 + 2 * cx.t;
            int h = n >> 6, c = n & 63;
            float v0 = acc[mt][nt][0], v1 = acc[mt][nt][1];
            float v2 = acc[mt][nt][2], v3 = acc[mt][nt][3];
            if (z == 2) {
                __half* dv = dst + (((size_t)(b * HN + h)) * DK + c) * SSZ + s;
                dv[0]       = __float2half_rn(v0);
                dv[SSZ]     = __float2half_rn(v1);
                dv[8]       = __float2half_rn(v2);
                dv[SSZ + 8] = __float2half_rn(v3);
            } else {
                int p = c >> 1;
                float ca0 = g_cos[(s << 5) | p],       sa0 = g_sin[(s << 5) | p];
                float ca1 = g_cos[((s + 8) << 5) | p], sa1 = g_sin[((s + 8) << 5) | p];
                float r0 = v0 * ca0 - v1 * sa0;
                float r1 = v0 * sa0 + v1 * ca0;
                float r2 = v2 * ca1 - v3 * sa1;
                float r3 = v2 * sa1 + v3 * ca1;
                if (z == 0) { r0 *= qsc; r1 *= qsc; r2 *= qsc; r3 *= qsc; }
                __half* base = dst + (((size_t)(b * HN + h) * SSZ)) * DK + c;
                *(__half2*)(base + (size_t)s * DK)       = __floats2half2_rn(r0, r1);
                *(__half2*)(base + (size_t)(s + 8) * DK) = __floats2half2_rn(r2, r3);
            }
        }
    }
}

// Output projection: out = g_O @ g_Wo^T, fp32 result
__global__ __launch_bounds__(128) void gemm_out_kernel(float* __restrict__ C)
{
    extern __shared__ __half smh[];
    __half* As = smh;
    __half* Bs = smh + GSTG * GBUF;

    GemmCtx cx = make_gemm_ctx();
    const int m0 = blockIdx.y * 128, n0 = blockIdx.x * 128;

    float acc[4][8][4];
#pragma unroll
    for (int i = 0; i < 4; i++)
#pragma unroll
        for (int j = 0; j < 8; j++)
#pragma unroll
            for (int k = 0; k < 4; k++) acc[i][j][k] = 0.f;

    gemm_main(g_O, g_Wo, m0, n0, acc, As, Bs, cx);

#pragma unroll
    for (int mt = 0; mt < 4; mt++) {
        int m = m0 + cx.wm + mt * 16 + cx.g;
#pragma unroll
        for (int nt = 0; nt < 8; nt++) {
            int n = n0 + cx.wn + nt * 8 + 2 * cx.t;
            *(float2*)(C + (size_t)m * 1024 + n)       = make_float2(acc[mt][nt][0], acc[mt][nt][1]);
            *(float2*)(C + (size_t)(m + 8) * 1024 + n) = make_float2(acc[mt][nt][2], acc[mt][nt][3]);
        }
    }
}

// ---------------------------------------------------------------------------
// fp16 flash attention (R11 geometry + ldmatrix): 128 thr / 4 warps,
// BQ=128, BK=64, dk=64. Q frags direct from gmem; V transposed.
// smem: sP[128][72], sK[2][64][72], sVt[2][64][72] halves (54 KB).
// AST=72 -> ldmatrix rows hit banks 4r (conflict-free).
// ---------------------------------------------------------------------------
#define AST 72     // halves per smem row
#define AKBUF (64*AST)

__global__ __launch_bounds__(128) void attn_kernel() {
    extern __shared__ __half smh[];
    __half* sP  = smh;                   // 128*72
    __half* sK0 = smh + 128*AST;         // 2 x 64*72
    __half* sV0 = smh + 128*AST + 2*AKBUF;

    const int tid = threadIdx.x;
    const int w = tid >> 5;
    const int lane = tid & 31;
    const int g = lane >> 2, t = lane & 3;
    // ldmatrix lane offsets
    const int arow = ((lane >> 3) & 1) * 8 + (lane & 7);
    const int akh  = (lane >> 4) * 8;
    const int brow = ((lane >> 4) & 1) * 8 + (lane & 7);
    const int bkh  = ((lane >> 3) & 1) * 8;

    const int qb = (int)gridDim.x - 1 - (int)blockIdx.x;   // heavy CTAs first
    const int bh = blockIdx.y;
    const __half* Qg  = g_Q + (size_t)bh * SSZ * DK;
    const __half* Kg  = g_K + (size_t)bh * SSZ * DK;
    const __half* Vtg = g_V + (size_t)bh * DK * SSZ;       // [dk][S]
    const int kb_max = 2 * qb + 1;
    const int warp_row_max = qb * 128 + w * 32 + 31;

    const unsigned p_byte  = (unsigned)__cvta_generic_to_shared(sP);
    const unsigned k0_byte = (unsigned)__cvta_generic_to_shared(sK0);
    const unsigned v0_byte = (unsigned)__cvta_generic_to_shared(sV0);

    // prologue: issue K/V block 0 loads (64 rows x 64 halves each)
#pragma unroll
    for (int i = 0; i < 4; i++) {
        int e = i * 128 + tid;
        int r = e >> 3, c8 = (e & 7) << 3;
        cpa16(&sK0[r * AST + c8], Kg + (size_t)r * DK + c8);
        cpa16(&sV0[r * AST + c8], Vtg + (size_t)r * SSZ + c8);
    }
    cpa_commit();

    // Q fragments direct from gmem (already scaled, fp16)
    unsigned qf[2][4][4];
#pragma unroll
    for (int mt = 0; mt < 2; mt++) {
        int q0 = qb * 128 + w * 32 + mt * 16 + g;
#pragma unroll
        for (int ks = 0; ks < 4; ks++) {
            const __half* p = Qg + (size_t)q0 * DK + ks * 16 + 2 * t;
            qf[mt][ks][0] = *(const unsigned*)(p);
            qf[mt][ks][1] = *(const unsigned*)(p + 8 * DK);
            qf[mt][ks][2] = *(const unsigned*)(p + 8);
            qf[mt][ks][3] = *(const unsigned*)(p + 8 * DK + 8);
        }
    }

    float mrun[2][2] = {{-1e30f, -1e30f}, {-1e30f, -1e30f}};
    float lrun[2][2] = {{0.f, 0.f}, {0.f, 0.f}};
    float oacc[2][8][4];
#pragma unroll
    for (int mt = 0; mt < 2; mt++)
#pragma unroll
        for (int nt = 0; nt < 8; nt++)
#pragma unroll
            for (int k = 0; k < 4; k++) oacc[mt][nt][k] = 0.f;

    for (int kb = 0; kb <= kb_max; kb++) {
        __syncthreads();   // buffer (kb+1)&1 free
        if (kb < kb_max) {
            __half* sK = sK0 + ((kb + 1) & 1) * AKBUF;
            __half* sV = sV0 + ((kb + 1) & 1) * AKBUF;
#pragma unroll
            for (int i = 0; i < 4; i++) {
                int e = i * 128 + tid;
                int r = e >> 3, c8 = (e & 7) << 3;
                cpa16(&sK[r * AST + c8], Kg + (size_t)((kb + 1) * 64 + r) * DK + c8);
                cpa16(&sV[r * AST + c8], Vtg + (size_t)r * SSZ + (kb + 1) * 64 + c8);
            }
        }
        cpa_commit();
        cpa_wait<1>();
        __syncthreads();

        // whole-warp skip: entire q-tile above the diagonal
        if (kb * 64 > warp_row_max) continue;

        const unsigned k_byte = k0_byte + (kb & 1) * AKBUF * 2;
        const unsigned v_byte = v0_byte + (kb & 1) * AKBUF * 2;

        // S = Q K^T : 4 k16-steps over dk, 8 n-tiles over kv (ldmatrix K)
        float s[2][8][4];
#pragma unroll
        for (int mt = 0; mt < 2; mt++)
#pragma unroll
            for (int nt = 0; nt < 8; nt++)
#pragma unroll
                for (int k = 0; k < 4; k++) s[mt][nt][k] = 0.f;

#pragma unroll
        for (int ks = 0; ks < 4; ks++) {
            unsigned kf[8][2];
#pragma unroll
            for (int np = 0; np < 4; np++) {
                unsigned addr = k_byte +
                    (unsigned)(((np*16 + brow) * AST + ks*16 + bkh) * 2);
                ldsm4(kf[2*np][0], kf[2*np][1], kf[2*np+1][0], kf[2*np+1][1], addr);
            }
#pragma unroll
            for (int nt = 0; nt < 8; nt++) {
                mma16(s[0][nt], qf[0][ks], kf[nt]);
                mma16(s[1][nt], qf[1][ks], kf[nt]);
            }
        }

        // causal mask
        if (kb >= 2 * qb) {
#pragma unroll
            for (int mt = 0; mt < 2; mt++) {
                int qg = qb * 128 + w * 32 + mt * 16 + g;
#pragma unroll
                for (int nt = 0; nt < 8; nt++) {
                    int col = kb * 64 + nt * 8 + 2 * t;
                    if (col     > qg)     s[mt][nt][0] = -1e30f;
                    if (col + 1 > qg)     s[mt][nt][1] = -1e30f;
                    if (col     > qg + 8) s[mt][nt][2] = -1e30f;
                    if (col + 1 > qg + 8) s[mt][nt][3] = -1e30f;
                }
            }
        }

        __syncwarp();   // this warp's prior PV reads of its P rows done

        // online softmax (exp2 domain), deferred l-reduction
#pragma unroll
        for (int mt = 0; mt < 2; mt++) {
            const int qr = w * 32 + mt * 16 + g;
#pragma unroll
            for (int r = 0; r < 2; r++) {
                float mx = -1e30f;
#pragma unroll
                for (int nt = 0; nt < 8; nt++)
                    mx = fmaxf(mx, fmaxf(s[mt][nt][2*r], s[mt][nt][2*r + 1]));
                mx = fmaxf(mx, __shfl_xor_sync(0xffffffffu, mx, 1));
                mx = fmaxf(mx, __shfl_xor_sync(0xffffffffu, mx, 2));
                float mnew = fmaxf(mrun[mt][r], mx);
                float corr = ex2(mrun[mt][r] - mnew);
                float rs = 0.f;
                __half* prow = sP + (qr + 8 * r) * AST;
#pragma unroll
                for (int nt = 0; nt < 8; nt++) {
                    float p0 = ex2(s[mt][nt][2*r]     - mnew);
                    float p1 = ex2(s[mt][nt][2*r + 1] - mnew);
                    rs += p0 + p1;
                    *(__half2*)(prow + nt * 8 + 2 * t) = __floats2half2_rn(p0, p1);
                }
                lrun[mt][r] = lrun[mt][r] * corr + rs;
                mrun[mt][r] = mnew;
#pragma unroll
                for (int nt = 0; nt < 8; nt++) {
                    oacc[mt][nt][2*r]     *= corr;
                    oacc[mt][nt][2*r + 1] *= corr;
                }
            }
        }
        __syncwarp();

        // O += P V : ldmatrix P (A-style) and V (B-style)
#pragma unroll
        for (int ks = 0; ks < 4; ks++) {
            unsigned pf[2][4];
#pragma unroll
            for (int mt = 0; mt < 2; mt++) {
                unsigned addr = p_byte +
                    (unsigned)(((w*32 + mt*16 + arow) * AST + ks*16 + akh) * 2);
                ldsm4(pf[mt][0], pf[mt][1], pf[mt][2], pf[mt][3], addr);
            }
            unsigned vf[8][2];
#pragma unroll
            for (int np = 0; np < 4; np++) {
                unsigned addr = v_byte +
                    (unsigned)(((np*16 + brow) * AST + ks*16 + bkh) * 2);
                ldsm4(vf[2*np][0], vf[2*np][1], vf[2*np+1][0], vf[2*np+1][1], addr);
            }
#pragma unroll
            for (int nt = 0; nt < 8; nt++) {
                mma16(oacc[0][nt], pf[0], vf[nt]);
                mma16(oacc[1][nt], pf[1], vf[nt]);
            }
        }
    }

    // epilogue: reduce deferred row sums, normalize, store fp16 to [B,S,D]
    const int b = bh >> 4;
    const int h = bh & 15;
#pragma unroll
    for (int mt = 0; mt < 2; mt++) {
#pragma unroll
        for (int r = 0; r < 2; r++) {
            float lsum = lrun[mt][r];
            lsum += __shfl_xor_sync(0xffffffffu, lsum, 1);
            lsum += __shfl_xor_sync(0xffffffffu, lsum, 2);
            float inv = 1.f / lsum;
            int q = qb * 128 + w * 32 + mt * 16 + g + 8 * r;
            __half* dst = g_O + ((size_t)b * SSZ + q) * DSZ + h * DK;
#pragma unroll
            for (int nt = 0; nt < 8; nt++)
                *(__half2*)(dst + nt * 8 + 2 * t) =
                    __floats2half2_rn(oacc[mt][nt][2*r] * inv,
                                      oacc[mt][nt][2*r + 1] * inv);
        }
    }
}

// ---------------------------------------------------------------------------
extern "C" void kernel_launch(void* const* d_in, const int* in_sizes, int n_in,
                              void* d_out, int out_size) {
    (void)in_sizes; (void)n_in; (void)out_size;
    const float* x  = (const float*)d_in[0];
    const float* Wq = (const float*)d_in[1];
    const float* Wk = (const float*)d_in[2];
    const float* Wv = (const float*)d_in[3];
    const float* Wo = (const float*)d_in[4];
    float* out = (float*)d_out;

    const int gemm_smem = 2 * GSTG * GBUF * (int)sizeof(__half);   // 61440 B
    cudaFuncSetAttribute(gemm_qkv_kernel, cudaFuncAttributeMaxDynamicSharedMemorySize, gemm_smem);
    cudaFuncSetAttribute(gemm_out_kernel, cudaFuncAttributeMaxDynamicSharedMemorySize, gemm_smem);
    const int attn_smem = (128*AST + 4*AKBUF) * (int)sizeof(__half);  // 55296 B
    cudaFuncSetAttribute(attn_kernel, cudaFuncAttributeMaxDynamicSharedMemorySize, attn_smem);

    rope_table_kernel<<<(SSZ * NPAIR + 255) / 256, 256>>>();

    const int NTOT8 = NX8 + 4 * NW8;
    cast_all_kernel<<<(NTOT8 + 255)/256, 256>>>(
        (const float4*)x, (const float4*)Wq, (const float4*)Wk,
        (const float4*)Wv, (const float4*)Wo);

    gemm_qkv_kernel<<<dim3(8, 32, 3), 128, gemm_smem>>>();
    attn_kernel<<<dim3(SSZ / 128, BSZ * HN), 128, attn_smem>>>();
    gemm_out_kernel<<<dim3(8, 32), 128, gemm_smem>>>(out);
}